// round 6
// baseline (speedup 1.0000x reference)
#include <cuda_runtime.h>
#include <math.h>

// out[b,c,h,w] = prod_{p=1..24} cos(x_p + w_p), 5x5 'same' window.
// cos(x+w_p) = cos(w_p) * (cos x - tan(w_p) sin x)
// => out = scale * prod_{p>=1} fma(-t_p, sin x, cos x),  scale = prod cos(w_p).
// Packed f32x2 over column pairs (j, j+32): weights broadcast-packed once in
// prep; smem tile holds ((c_k,c_k+32),(s_k,s_k+32)) so one LDS.128 feeds one
// fma.rn.f32x2 per factor. Padded pixels -> (c,s)=(1,0) => factor 1.

typedef unsigned long long u64;

#define HW    64
#define PLANE (HW * HW)
#define TWP   36   // column pairs k: pixel cols (k-2, k+30) cover -2..65
#define TR    36   // 32 output rows + 2*2 halo

__device__ u64   g_nt2[25];   // (-tan w_p, -tan w_p) packed; p=0 unused
__device__ float g_scale;     // prod_{p=1..24} cos(w_p)

__global__ void prep_kernel(const float* __restrict__ w)
{
    __shared__ float cwsh[25];
    const int p = threadIdx.x;
    if (p < 25) {
        float s, c;
        sincosf(w[p], &s, &c);          // accurate; only 25 values
        const float nt = -s / c;
        const unsigned b = __float_as_uint(nt);
        g_nt2[p] = ((u64)b << 32) | (u64)b;
        cwsh[p] = c;
    }
    __syncwarp();
    if (p == 0) {
        float sc = 1.0f;
#pragma unroll
        for (int q = 1; q < 25; ++q) sc *= cwsh[q];
        g_scale = sc;
    }
}

__device__ __forceinline__ u64 pack2(float lo, float hi) {
    u64 r; asm("mov.b64 %0, {%1, %2};" : "=l"(r) : "f"(lo), "f"(hi)); return r;
}
__device__ __forceinline__ void unpack2(u64 v, float& lo, float& hi) {
    asm("mov.b64 {%0, %1}, %2;" : "=f"(lo), "=f"(hi) : "l"(v));
}
__device__ __forceinline__ u64 ffma2(u64 a, u64 b, u64 c) {
    u64 d; asm("fma.rn.f32x2 %0, %1, %2, %3;" : "=l"(d) : "l"(a), "l"(b), "l"(c)); return d;
}
__device__ __forceinline__ u64 fmul2(u64 a, u64 b) {
    u64 d; asm("mul.rn.f32x2 %0, %1, %2;" : "=l"(d) : "l"(a), "l"(b)); return d;
}

__global__ __launch_bounds__(128, 6)
void quanv_kernel(const float* __restrict__ x,
                  float* __restrict__ out)
{
    // tile[r][k] = ( pack(cos_k, cos_k32), pack(sin_k, sin_k32) )
    __shared__ ulonglong2 tile[TR][TWP];

    const int blk   = blockIdx.x;
    const int plane = blk >> 1;
    const int base  = (blk & 1) * 32;          // first output row of this half
    const float* xp = x + (size_t)plane * PLANE;
    float* op = out + (size_t)plane * PLANE;
    const int tid = threadIdx.x;

    // Broadcast-packed weights -> registers (uniform loads, L1 broadcast).
    u64 nt[25];
#pragma unroll
    for (int p = 1; p < 25; ++p) nt[p] = g_nt2[p];
    const float scale = g_scale;

    // Build tile: 36 rows x 36 col-pairs. Pixel pair cols (k-2, k+30).
    for (int idx = tid; idx < TR * TWP; idx += 128) {
        const int row = idx / TWP;
        const int k   = idx - row * TWP;
        const int gi  = base + row - 2;
        const int c0  = k - 2;
        const int c1  = k + 30;
        float xa = 0.0f, xb = 0.0f;
        const bool rok = (unsigned)gi < (unsigned)HW;
        if (rok && (unsigned)c0 < (unsigned)HW) xa = xp[gi * HW + c0];
        if (rok && (unsigned)c1 < (unsigned)HW) xb = xp[gi * HW + c1];
        float sa, ca, sb, cb;
        __sincosf(xa, &sa, &ca);
        __sincosf(xb, &sb, &cb);
        tile[row][k] = make_ulonglong2(pack2(ca, cb), pack2(sa, sb));
    }
    __syncthreads();

    // Thread = (col-pair j, segment of 8 output rows). Walk 12 tile rows; at
    // walk r, variant di feeds pending output i = r - di; retire at di==4.
    const int j   = tid & 31;      // col-pair 0..31 -> output cols j, j+32
    const int seg = tid >> 5;      // 0..3 -> output rows seg*8 .. seg*8+7

    u64 acc[8];

#pragma unroll
    for (int r = 0; r < 12; ++r) {
        const int tr = seg * 8 + r;
#pragma unroll
        for (int dj = 0; dj < 5; ++dj) {
            const ulonglong2 v = tile[tr][j + dj];   // one LDS.128
#pragma unroll
            for (int di = 0; di < 5; ++di) {
                const int i = r - di;                // output index in segment
                if (i < 0 || i >= 8) continue;
                const int p = di * 5 + dj;
                if (p == 0) continue;                // Z_0 wire excluded
                const u64 f = ffma2(nt[p], v.y, v.x);
                acc[i] = (di == 0 && dj == 1) ? f : fmul2(acc[i], f);
            }
        }
        const int idone = r - 4;                     // output completed this row
        if (idone >= 0) {
            float lo, hi;
            unpack2(acc[idone], lo, hi);
            const int orow = base + seg * 8 + idone;
            op[orow * HW + j]      = lo * scale;
            op[orow * HW + j + 32] = hi * scale;
        }
    }
}

extern "C" void kernel_launch(void* const* d_in, const int* in_sizes, int n_in,
                              void* d_out, int out_size)
{
    const float* x = (const float*)d_in[0];
    const float* w = (const float*)d_in[1];
    float* out = (float*)d_out;

    const int planes = in_sizes[0] / PLANE;   // B*C = 512

    prep_kernel<<<1, 32>>>(w);
    quanv_kernel<<<planes * 2, 128>>>(x, out);
}

// round 7
// speedup vs baseline: 1.0429x; 1.0429x over previous
#include <cuda_runtime.h>
#include <math.h>

// out[b,c,h,w] = prod_{p=1..24} cos(x_p + w_p), 5x5 'same' window.
// cos(x+w_p) = cos(w_p) * (cos x - tan(w_p) sin x)
// => out = scale * prod_{p>=1} fmaf(-tan w_p, sin x, cos x), scale = prod cos w_p.
// Sliding window: thread owns column j, walks tile rows; per row computes the
// 5 weight-row variants H_di and multiplies each into pending output i = r-di.
// Weights live in __constant__ -> ptxas LDCU/UR path (FFMA with uniform-reg
// operand), freeing ~24 GPRs vs register-resident weights.

#define HW    64
#define PLANE (HW * HW)
#define TW    68   // 64 + 2*2 col halo
#define TR    36   // 32 output rows + 2*2 row halo

__device__   float g_stage[26];   // [p]= -tan(w_p) (p=1..24), [25]= prod cos
__constant__ float c_w[26];

__global__ void prep_kernel(const float* __restrict__ w)
{
    __shared__ float cwsh[25];
    const int p = threadIdx.x;
    if (p < 25) {
        float s, c;
        sincosf(w[p], &s, &c);      // accurate; only 25 values
        g_stage[p] = -s / c;
        cwsh[p] = c;
    }
    __syncwarp();
    if (p == 0) {
        float sc = 1.0f;
#pragma unroll
        for (int q = 1; q < 25; ++q) sc *= cwsh[q];
        g_stage[25] = sc;
    }
}

__global__ __launch_bounds__(128, 10)
void quanv_kernel(const float* __restrict__ x,
                  float* __restrict__ out)
{
    __shared__ float2 scs[TR][TW];   // (cos x, sin x); padded cells -> (1,0)

    const int blk   = blockIdx.x;
    const int plane = blk >> 1;
    const int base  = (blk & 1) * 32;          // first output row of this half
    const float* xp = x + (size_t)plane * PLANE;
    float* op = out + (size_t)plane * PLANE;
    const int tid = threadIdx.x;

    // Build 36x68 halo tile: tile row 0 = global row base-2, col 0 = global -2.
    for (int idx = tid; idx < TR * TW; idx += 128) {
        const int i  = idx / TW;
        const int j  = idx - i * TW;
        const int gi = base + i - 2;
        const int gj = j - 2;
        float v = 0.0f;
        if ((unsigned)gi < (unsigned)HW && (unsigned)gj < (unsigned)HW)
            v = xp[gi * HW + gj];
        float s, c;
        __sincosf(v, &s, &c);
        scs[i][j] = make_float2(c, s);
    }
    __syncthreads();

    const float scale = c_w[25];

    // Thread = (column j, segment of 16 output rows). Walk 20 tile rows;
    // at walk index r, variant di feeds pending output i = r - di.
    const int j  = tid & 63;          // 0..63
    const int i0 = (tid >> 6) * 16;   // 0 or 16 (relative to base)

    float acc[16];

#pragma unroll
    for (int r = 0; r < 20; ++r) {
        const int tr = i0 + r;
        const float2 v0 = scs[tr][j + 0];
        const float2 v1 = scs[tr][j + 1];
        const float2 v2 = scs[tr][j + 2];
        const float2 v3 = scs[tr][j + 3];
        const float2 v4 = scs[tr][j + 4];

#pragma unroll
        for (int di = 0; di < 5; ++di) {
            const int i = r - di;                  // output index in segment
            if (i < 0 || i >= 16) continue;
            float h;
            if (di == 0) {
                // p = 0 (Z_0 wire) excluded: dj = 1..4 only.
                h = (fmaf(c_w[1], v1.y, v1.x) * fmaf(c_w[2], v2.y, v2.x))
                  * (fmaf(c_w[3], v3.y, v3.x) * fmaf(c_w[4], v4.y, v4.x));
            } else {
                const int b = di * 5;
                h = (fmaf(c_w[b    ], v0.y, v0.x) * fmaf(c_w[b + 1], v1.y, v1.x))
                  * (fmaf(c_w[b + 2], v2.y, v2.x) * fmaf(c_w[b + 3], v3.y, v3.x));
                h *= fmaf(c_w[b + 4], v4.y, v4.x);
            }
            acc[i] = (di == 0) ? h : acc[i] * h;
            if (di == 4)   // output complete -> store, free the register
                op[(base + i0 + i) * HW + j] = acc[i] * scale;
        }
    }
}

extern "C" void kernel_launch(void* const* d_in, const int* in_sizes, int n_in,
                              void* d_out, int out_size)
{
    const float* x = (const float*)d_in[0];
    const float* w = (const float*)d_in[1];
    float* out = (float*)d_out;

    const int planes = in_sizes[0] / PLANE;   // B*C = 512

    prep_kernel<<<1, 32>>>(w);

    // Stage -> __constant__ (D2D memcpy node; graph-capturable).
    void* stage_ptr = nullptr;
    cudaGetSymbolAddress(&stage_ptr, g_stage);
    cudaMemcpyToSymbolAsync(c_w, stage_ptr, 26 * sizeof(float), 0,
                            cudaMemcpyDeviceToDevice, 0);

    quanv_kernel<<<planes * 2, 128>>>(x, out);
}